// round 8
// baseline (speedup 1.0000x reference)
#include <cuda_runtime.h>
#include <cuda_fp16.h>
#include <math.h>

#define B_TOT 32768
#define F_TOT 512
#define H_TOT 10
#define H_F16 6              // h in [0,H_F16) via f16x2 MUFU; rest via smem LUT

#define THREADS 512          // 16 warps; warp w covers features [32w, 32w+32)
#define NWARP (THREADS / 32)
#define CHUNK 32             // batches per block
#define NB 4                 // batches per inner group

#define LUT_N 320            // [-5, 5], 32 segments per unit
#define LUT_SCALE 32.0f
#define LUT_BIAS  160.0f     // (z+5)*32
#define LUT_ZMIN  (-5.0f)
#define LUT_ZMAX  (4.984375f)   // keeps index <= 319

__device__ __forceinline__ __half2 tanh2_fast(__half2 v) {
    unsigned a = *reinterpret_cast<unsigned*>(&v), r;
    asm("tanh.approx.f16x2 %0, %1;" : "=r"(r) : "r"(a));
    return *reinterpret_cast<__half2*>(&r);
}

__device__ __forceinline__ float warp_sum(float v) {
#pragma unroll
    for (int off = 16; off > 0; off >>= 1)
        v += __shfl_xor_sync(0xFFFFFFFFu, v, off);
    return v;
}

// ---------------------------------------------------------------------------
// Lane owns one feature. 6 hidden units run tanh on MUFU (f16x2 pairs);
// 4 hidden units run tanh via a piecewise-linear smem LUT (no MUFU):
//   t = fma(slope, z, intercept) after clamped index lookup.
// fp32 accumulation throughout; folded warp reduction per 4-batch group.
// ---------------------------------------------------------------------------
__global__ __launch_bounds__(THREADS, 2)
void neural_unilasso_kernel(const float* __restrict__ x,
                            const float* __restrict__ W1,
                            const float* __restrict__ b1,
                            const float* __restrict__ W2,
                            const float* __restrict__ b2,
                            const float* __restrict__ theta,
                            const float* __restrict__ bias,
                            float* __restrict__ y,
                            float* __restrict__ y_theta) {
    __shared__ float2 lut[LUT_N];        // 2.5 KB: (intercept, slope) per segment
    __shared__ float part[CHUNK * 17];   // [batch][warp], padded stride
    __shared__ float s_red[NWARP];
    __shared__ float s_base;

    const int tid  = threadIdx.x;
    const int lane = tid & 31;
    const int warp = tid >> 5;
    const int f    = warp * 32 + lane;   // THREADS == F_TOT

    // ---- build LUT (once per block; 320 tanhf on MUFU, trivial) ----
    if (tid < LUT_N) {
        float z0 = LUT_ZMIN + (float)tid * (1.0f / LUT_SCALE);
        float z1 = z0 + (1.0f / LUT_SCALE);
        float y0 = tanhf(z0), y1 = tanhf(z1);
        float slope = (y1 - y0) * LUT_SCALE;
        lut[tid] = make_float2(fmaf(-slope, z0, y0), slope);  // intercept, slope
    }

    // ---- prologue: params + softplus + csum ----
    const float th = theta[f];
    const float st = log1pf(expf(th));           // softplus
    if (blockIdx.x == 0) y_theta[f] = st;        // nn_theta output

    __half2 w1h[H_F16], b1h[H_F16];
    float   w2a[H_F16];                           // fp32 w2*st for f16 path
    float   w1r[H_TOT - H_F16], b1r[H_TOT - H_F16], w2r[H_TOT - H_F16];
#pragma unroll
    for (int h = 0; h < H_F16; h++) {
        float w1 = __ldg(&W1[f * H_TOT + h]);
        float bb = __ldg(&b1[f * H_TOT + h]);
        w1h[h] = __floats2half2_rn(w1, w1);
        b1h[h] = __floats2half2_rn(bb, bb);
        w2a[h] = __ldg(&W2[f * H_TOT + h]) * st;
    }
#pragma unroll
    for (int h = 0; h < H_TOT - H_F16; h++) {
        w1r[h] = __ldg(&W1[f * H_TOT + H_F16 + h]);
        b1r[h] = __ldg(&b1[f * H_TOT + H_F16 + h]);
        w2r[h] = __ldg(&W2[f * H_TOT + H_F16 + h]) * st;
    }
    {
        float c = warp_sum(b2[f] * st);
        if (lane == 0) s_red[warp] = c;
        __syncthreads();                 // also publishes lut[]
        if (tid == 0) {
            float s = bias[0];
#pragma unroll
            for (int w = 0; w < NWARP; w++) s += s_red[w];
            s_base = s;
        }
        __syncthreads();
    }

    const int bchunk = blockIdx.x * CHUNK;
    const float* xp = x + (size_t)bchunk * F_TOT + f;

    // depth-1 prefetch (R6-proven)
    float xc0 = __ldg(xp + 0 * F_TOT);
    float xc1 = __ldg(xp + 1 * F_TOT);
    float xc2 = __ldg(xp + 2 * F_TOT);
    float xc3 = __ldg(xp + 3 * F_TOT);

#pragma unroll 1
    for (int g = 0; g < CHUNK; g += NB) {
        float xn0, xn1, xn2, xn3;
        if (g + NB < CHUNK) {
            xn0 = __ldg(xp + (size_t)(g + NB + 0) * F_TOT);
            xn1 = __ldg(xp + (size_t)(g + NB + 1) * F_TOT);
            xn2 = __ldg(xp + (size_t)(g + NB + 2) * F_TOT);
            xn3 = __ldg(xp + (size_t)(g + NB + 3) * F_TOT);
        }

        float a0 = 0.f, a1 = 0.f, a2 = 0.f, a3 = 0.f;

        // ---- LUT path: h = H_F16 .. H_TOT-1, fp32, no MUFU ----
#pragma unroll
        for (int h = 0; h < H_TOT - H_F16; h++) {
            float z0 = fmaf(xc0, w1r[h], b1r[h]);
            float z1 = fmaf(xc1, w1r[h], b1r[h]);
            float z2 = fmaf(xc2, w1r[h], b1r[h]);
            float z3 = fmaf(xc3, w1r[h], b1r[h]);
            z0 = fminf(fmaxf(z0, LUT_ZMIN), LUT_ZMAX);
            z1 = fminf(fmaxf(z1, LUT_ZMIN), LUT_ZMAX);
            z2 = fminf(fmaxf(z2, LUT_ZMIN), LUT_ZMAX);
            z3 = fminf(fmaxf(z3, LUT_ZMIN), LUT_ZMAX);
            int i0 = (int)fmaf(z0, LUT_SCALE, LUT_BIAS);
            int i1 = (int)fmaf(z1, LUT_SCALE, LUT_BIAS);
            int i2 = (int)fmaf(z2, LUT_SCALE, LUT_BIAS);
            int i3 = (int)fmaf(z3, LUT_SCALE, LUT_BIAS);
            float2 e0 = lut[i0];
            float2 e1 = lut[i1];
            float2 e2 = lut[i2];
            float2 e3 = lut[i3];
            float t0 = fmaf(e0.y, z0, e0.x);
            float t1 = fmaf(e1.y, z1, e1.x);
            float t2 = fmaf(e2.y, z2, e2.x);
            float t3 = fmaf(e3.y, z3, e3.x);
            a0 = fmaf(t0, w2r[h], a0);
            a1 = fmaf(t1, w2r[h], a1);
            a2 = fmaf(t2, w2r[h], a2);
            a3 = fmaf(t3, w2r[h], a3);
        }

        // ---- f16x2 MUFU path: h = 0 .. H_F16-1 ----
        const __half2 x01 = __floats2half2_rn(xc0, xc1);
        const __half2 x23 = __floats2half2_rn(xc2, xc3);
#pragma unroll
        for (int h = 0; h < H_F16; h++) {
            __half2 p01 = __hfma2(x01, w1h[h], b1h[h]);
            __half2 p23 = __hfma2(x23, w1h[h], b1h[h]);
            __half2 t01 = tanh2_fast(p01);
            __half2 t23 = tanh2_fast(p23);
            float2 f01 = __half22float2(t01);
            float2 f23 = __half22float2(t23);
            a0 = fmaf(f01.x, w2a[h], a0);
            a1 = fmaf(f01.y, w2a[h], a1);
            a2 = fmaf(f23.x, w2a[h], a2);
            a3 = fmaf(f23.y, w2a[h], a3);
        }

        // folded 4-accumulator warp reduction (11 SHFL)
        a0 += __shfl_xor_sync(0xFFFFFFFFu, a0, 16);
        a1 += __shfl_xor_sync(0xFFFFFFFFu, a1, 16);
        a2 += __shfl_xor_sync(0xFFFFFFFFu, a2, 16);
        a3 += __shfl_xor_sync(0xFFFFFFFFu, a3, 16);
        a0 += __shfl_xor_sync(0xFFFFFFFFu, a0, 8);
        a1 += __shfl_xor_sync(0xFFFFFFFFu, a1, 8);
        a2 += __shfl_xor_sync(0xFFFFFFFFu, a2, 8);
        a3 += __shfl_xor_sync(0xFFFFFFFFu, a3, 8);
        int q = (lane >> 3) & 3;
        float c = (q == 0) ? a0 : (q == 1) ? a1 : (q == 2) ? a2 : a3;
        c += __shfl_xor_sync(0xFFFFFFFFu, c, 4);
        c += __shfl_xor_sync(0xFFFFFFFFu, c, 2);
        c += __shfl_xor_sync(0xFFFFFFFFu, c, 1);
        if ((lane & 7) == 0)
            part[(g + q) * 17 + warp] = c;

        xc0 = xn0; xc1 = xn1; xc2 = xn2; xc3 = xn3;
    }
    __syncthreads();

    if (tid < CHUNK) {
        float s = s_base;
#pragma unroll
        for (int w = 0; w < NWARP; w++) s += part[tid * 17 + w];
        y[bchunk + tid] = s;
    }
}

// ---------------------------------------------------------------------------
// kernel_launch: inputs in setup_inputs order:
//   0:x (B,F)  1:W1 (F,H)  2:b1 (F,H)  3:W2 (F,H)  4:b2 (F)  5:theta (F)  6:bias (1)
// output: y_pred (B) then nn_theta (F), fp32.
// ---------------------------------------------------------------------------
extern "C" void kernel_launch(void* const* d_in, const int* in_sizes, int n_in,
                              void* d_out, int out_size) {
    const float* x     = (const float*)d_in[0];
    const float* W1    = (const float*)d_in[1];
    const float* b1    = (const float*)d_in[2];
    const float* W2    = (const float*)d_in[3];
    const float* b2    = (const float*)d_in[4];
    const float* theta = (const float*)d_in[5];
    const float* bias  = (const float*)d_in[6];
    float* out = (float*)d_out;

    neural_unilasso_kernel<<<B_TOT / CHUNK, THREADS>>>(
        x, W1, b1, W2, b2, theta, bias, out, out + B_TOT);
}

// round 9
// speedup vs baseline: 1.1773x; 1.1773x over previous
#include <cuda_runtime.h>
#include <cuda_fp16.h>
#include <math.h>

#define B_TOT 32768
#define F_TOT 512
#define H_TOT 10

#define THREADS 512          // 16 warps; warp w covers features [32w, 32w+32)
#define NWARP (THREADS / 32)
#define NB 4                 // batches per inner group (2 half2 pairs)
#define QB 16                // batches per work quantum
#define NQ (B_TOT / QB)      // 2048 quanta
#define GRID 296             // 2 CTAs x 148 SMs (work-stealing tolerates mismatch)

__device__ unsigned int g_ctr;

__device__ __forceinline__ __half2 tanh2_fast(__half2 v) {
    unsigned a = *reinterpret_cast<unsigned*>(&v), r;
    asm("tanh.approx.f16x2 %0, %1;" : "=r"(r) : "r"(a));
    return *reinterpret_cast<__half2*>(&r);
}

__device__ __forceinline__ float warp_sum(float v) {
#pragma unroll
    for (int off = 16; off > 0; off >>= 1)
        v += __shfl_xor_sync(0xFFFFFFFFu, v, off);
    return v;
}

__global__ void reset_kernel() { g_ctr = 0u; }

// ---------------------------------------------------------------------------
// Persistent kernel. Lane owns one feature; params in registers (R6 layout).
// Blocks steal 16-batch quanta via a global counter. Inner loop per h:
// 2 HFMA2 arg + 2 tanh2 + 2 cvt-pair + 4 fp32 FFMA acc.
// ---------------------------------------------------------------------------
__global__ __launch_bounds__(THREADS, 2)
void neural_unilasso_kernel(const float* __restrict__ x,
                            const float* __restrict__ W1,
                            const float* __restrict__ b1,
                            const float* __restrict__ W2,
                            const float* __restrict__ b2,
                            const float* __restrict__ theta,
                            const float* __restrict__ bias,
                            float* __restrict__ y,
                            float* __restrict__ y_theta) {
    __shared__ float part[QB * 17];      // [batch-in-quantum][warp]
    __shared__ float s_red[NWARP];
    __shared__ float s_base;
    __shared__ unsigned s_q;

    const int tid  = threadIdx.x;
    const int lane = tid & 31;
    const int warp = tid >> 5;
    const int f    = warp * 32 + lane;   // THREADS == F_TOT

    // ---- prologue (once per persistent block) ----
    const float th = theta[f];
    const float st = log1pf(expf(th));           // softplus
    if (blockIdx.x == 0) y_theta[f] = st;        // nn_theta output

    __half2 w1h[H_TOT], b1h[H_TOT];
    float w2r[H_TOT];
#pragma unroll
    for (int h = 0; h < H_TOT; h++) {
        float w1 = __ldg(&W1[f * H_TOT + h]);
        float bb = __ldg(&b1[f * H_TOT + h]);
        w1h[h] = __floats2half2_rn(w1, w1);
        b1h[h] = __floats2half2_rn(bb, bb);
        w2r[h] = __ldg(&W2[f * H_TOT + h]) * st; // fp32, exact scaling
    }
    {
        float c = warp_sum(b2[f] * st);
        if (lane == 0) s_red[warp] = c;
        __syncthreads();
        if (tid == 0) {
            float s = bias[0];
#pragma unroll
            for (int w = 0; w < NWARP; w++) s += s_red[w];
            s_base = s;
        }
    }

    // ---- persistent work-stealing loop ----
    for (;;) {
        if (tid == 0) s_q = atomicAdd(&g_ctr, 1u);
        __syncthreads();                 // publishes s_q; protects part[] reuse
        const unsigned q = s_q;
        if (q >= NQ) break;

        const int bchunk = (int)q * QB;
        const float* xp = x + (size_t)bchunk * F_TOT + f;

        // depth-1 prefetch across the 4 groups of this quantum
        float xc0 = __ldg(xp + 0 * F_TOT);
        float xc1 = __ldg(xp + 1 * F_TOT);
        float xc2 = __ldg(xp + 2 * F_TOT);
        float xc3 = __ldg(xp + 3 * F_TOT);

#pragma unroll 1
        for (int g = 0; g < QB; g += NB) {
            float xn0, xn1, xn2, xn3;
            if (g + NB < QB) {
                xn0 = __ldg(xp + (size_t)(g + NB + 0) * F_TOT);
                xn1 = __ldg(xp + (size_t)(g + NB + 1) * F_TOT);
                xn2 = __ldg(xp + (size_t)(g + NB + 2) * F_TOT);
                xn3 = __ldg(xp + (size_t)(g + NB + 3) * F_TOT);
            }

            const __half2 x01 = __floats2half2_rn(xc0, xc1);
            const __half2 x23 = __floats2half2_rn(xc2, xc3);

            float a0 = 0.f, a1 = 0.f, a2 = 0.f, a3 = 0.f;
#pragma unroll
            for (int h = 0; h < H_TOT; h++) {
                __half2 p01 = __hfma2(x01, w1h[h], b1h[h]);
                __half2 p23 = __hfma2(x23, w1h[h], b1h[h]);
                __half2 t01 = tanh2_fast(p01);
                __half2 t23 = tanh2_fast(p23);
                float2 f01 = __half22float2(t01);
                float2 f23 = __half22float2(t23);
                a0 = fmaf(f01.x, w2r[h], a0);
                a1 = fmaf(f01.y, w2r[h], a1);
                a2 = fmaf(f23.x, w2r[h], a2);
                a3 = fmaf(f23.y, w2r[h], a3);
            }

            // folded 4-accumulator warp reduction (11 SHFL)
            a0 += __shfl_xor_sync(0xFFFFFFFFu, a0, 16);
            a1 += __shfl_xor_sync(0xFFFFFFFFu, a1, 16);
            a2 += __shfl_xor_sync(0xFFFFFFFFu, a2, 16);
            a3 += __shfl_xor_sync(0xFFFFFFFFu, a3, 16);
            a0 += __shfl_xor_sync(0xFFFFFFFFu, a0, 8);
            a1 += __shfl_xor_sync(0xFFFFFFFFu, a1, 8);
            a2 += __shfl_xor_sync(0xFFFFFFFFu, a2, 8);
            a3 += __shfl_xor_sync(0xFFFFFFFFu, a3, 8);
            int qq = (lane >> 3) & 3;
            float c = (qq == 0) ? a0 : (qq == 1) ? a1 : (qq == 2) ? a2 : a3;
            c += __shfl_xor_sync(0xFFFFFFFFu, c, 4);
            c += __shfl_xor_sync(0xFFFFFFFFu, c, 2);
            c += __shfl_xor_sync(0xFFFFFFFFu, c, 1);
            if ((lane & 7) == 0)
                part[(g + qq) * 17 + warp] = c;

            xc0 = xn0; xc1 = xn1; xc2 = xn2; xc3 = xn3;
        }
        __syncthreads();                 // part[] complete for this quantum

        if (tid < QB) {
            float s = s_base;
#pragma unroll
            for (int w = 0; w < NWARP; w++) s += part[tid * 17 + w];
            y[bchunk + tid] = s;
        }
        // next iteration's post-grab __syncthreads orders part[] reuse
    }
}

// ---------------------------------------------------------------------------
// kernel_launch: inputs in setup_inputs order:
//   0:x (B,F)  1:W1 (F,H)  2:b1 (F,H)  3:W2 (F,H)  4:b2 (F)  5:theta (F)  6:bias (1)
// output: y_pred (B) then nn_theta (F), fp32.
// ---------------------------------------------------------------------------
extern "C" void kernel_launch(void* const* d_in, const int* in_sizes, int n_in,
                              void* d_out, int out_size) {
    const float* x     = (const float*)d_in[0];
    const float* W1    = (const float*)d_in[1];
    const float* b1    = (const float*)d_in[2];
    const float* W2    = (const float*)d_in[3];
    const float* b2    = (const float*)d_in[4];
    const float* theta = (const float*)d_in[5];
    const float* bias  = (const float*)d_in[6];
    float* out = (float*)d_out;

    reset_kernel<<<1, 1>>>();
    neural_unilasso_kernel<<<GRID, THREADS>>>(
        x, W1, b1, W2, b2, theta, bias, out, out + B_TOT);
}

// round 10
// speedup vs baseline: 1.2132x; 1.0305x over previous
#include <cuda_runtime.h>
#include <cuda_fp16.h>
#include <math.h>

#define B_TOT 32768
#define F_TOT 512
#define H_TOT 10

#define THREADS 512          // 16 warps; warp w covers features [32w, 32w+32)
#define NWARP (THREADS / 32)
#define NB 4                 // batches per inner group (2 half2 pairs)
#define QB 16                // batches per chunk
#define NQ (B_TOT / QB)      // 2048 chunks
#define GRID 296             // 2 CTAs x 148 SMs, single full wave

__device__ __forceinline__ __half2 tanh2_fast(__half2 v) {
    unsigned a = *reinterpret_cast<unsigned*>(&v), r;
    asm("tanh.approx.f16x2 %0, %1;" : "=r"(r) : "r"(a));
    return *reinterpret_cast<__half2*>(&r);
}

__device__ __forceinline__ float warp_sum(float v) {
#pragma unroll
    for (int off = 16; off > 0; off >>= 1)
        v += __shfl_xor_sync(0xFFFFFFFFu, v, off);
    return v;
}

// ---------------------------------------------------------------------------
// Static-persistent kernel. Lane owns one feature; params in registers.
// Block b statically owns chunks b, b+GRID, ... (no atomics, deterministic).
// part[] is parity double-buffered -> one __syncthreads per chunk.
// Inner loop per h: 2 HFMA2 arg + 2 tanh2 + 2 cvt-pair + 4 fp32 FFMA acc.
// ---------------------------------------------------------------------------
__global__ __launch_bounds__(THREADS, 2)
void neural_unilasso_kernel(const float* __restrict__ x,
                            const float* __restrict__ W1,
                            const float* __restrict__ b1,
                            const float* __restrict__ W2,
                            const float* __restrict__ b2,
                            const float* __restrict__ theta,
                            const float* __restrict__ bias,
                            float* __restrict__ y,
                            float* __restrict__ y_theta) {
    __shared__ float part[2][QB * 17];   // parity-buffered [batch][warp]
    __shared__ float s_red[NWARP];
    __shared__ float s_base;

    const int tid  = threadIdx.x;
    const int lane = tid & 31;
    const int warp = tid >> 5;
    const int f    = warp * 32 + lane;   // THREADS == F_TOT

    // ---- prologue (once per persistent block) ----
    const float th = theta[f];
    const float st = log1pf(expf(th));           // softplus
    if (blockIdx.x == 0) y_theta[f] = st;        // nn_theta output

    __half2 w1h[H_TOT], b1h[H_TOT];
    float w2r[H_TOT];
#pragma unroll
    for (int h = 0; h < H_TOT; h++) {
        float w1 = __ldg(&W1[f * H_TOT + h]);
        float bb = __ldg(&b1[f * H_TOT + h]);
        w1h[h] = __floats2half2_rn(w1, w1);
        b1h[h] = __floats2half2_rn(bb, bb);
        w2r[h] = __ldg(&W2[f * H_TOT + h]) * st; // fp32, exact scaling
    }
    {
        float c = warp_sum(b2[f] * st);
        if (lane == 0) s_red[warp] = c;
        __syncthreads();
        if (tid == 0) {
            float s = bias[0];
#pragma unroll
            for (int w = 0; w < NWARP; w++) s += s_red[w];
            s_base = s;
        }
        __syncthreads();
    }

    // ---- static-persistent chunk loop ----
    int parity = 0;
#pragma unroll 1
    for (int c = blockIdx.x; c < NQ; c += GRID, parity ^= 1) {
        const int bchunk = c * QB;
        const float* xp = x + (size_t)bchunk * F_TOT + f;
        float* pbuf = part[parity];

        // depth-1 prefetch across the 4 groups of this chunk
        float xc0 = __ldg(xp + 0 * F_TOT);
        float xc1 = __ldg(xp + 1 * F_TOT);
        float xc2 = __ldg(xp + 2 * F_TOT);
        float xc3 = __ldg(xp + 3 * F_TOT);

#pragma unroll 1
        for (int g = 0; g < QB; g += NB) {
            float xn0, xn1, xn2, xn3;
            if (g + NB < QB) {
                xn0 = __ldg(xp + (size_t)(g + NB + 0) * F_TOT);
                xn1 = __ldg(xp + (size_t)(g + NB + 1) * F_TOT);
                xn2 = __ldg(xp + (size_t)(g + NB + 2) * F_TOT);
                xn3 = __ldg(xp + (size_t)(g + NB + 3) * F_TOT);
            }

            const __half2 x01 = __floats2half2_rn(xc0, xc1);
            const __half2 x23 = __floats2half2_rn(xc2, xc3);

            float a0 = 0.f, a1 = 0.f, a2 = 0.f, a3 = 0.f;
#pragma unroll
            for (int h = 0; h < H_TOT; h++) {
                __half2 p01 = __hfma2(x01, w1h[h], b1h[h]);
                __half2 p23 = __hfma2(x23, w1h[h], b1h[h]);
                __half2 t01 = tanh2_fast(p01);
                __half2 t23 = tanh2_fast(p23);
                float2 f01 = __half22float2(t01);
                float2 f23 = __half22float2(t23);
                a0 = fmaf(f01.x, w2r[h], a0);
                a1 = fmaf(f01.y, w2r[h], a1);
                a2 = fmaf(f23.x, w2r[h], a2);
                a3 = fmaf(f23.y, w2r[h], a3);
            }

            // folded 4-accumulator warp reduction (11 SHFL)
            a0 += __shfl_xor_sync(0xFFFFFFFFu, a0, 16);
            a1 += __shfl_xor_sync(0xFFFFFFFFu, a1, 16);
            a2 += __shfl_xor_sync(0xFFFFFFFFu, a2, 16);
            a3 += __shfl_xor_sync(0xFFFFFFFFu, a3, 16);
            a0 += __shfl_xor_sync(0xFFFFFFFFu, a0, 8);
            a1 += __shfl_xor_sync(0xFFFFFFFFu, a1, 8);
            a2 += __shfl_xor_sync(0xFFFFFFFFu, a2, 8);
            a3 += __shfl_xor_sync(0xFFFFFFFFu, a3, 8);
            int q = (lane >> 3) & 3;
            float cc = (q == 0) ? a0 : (q == 1) ? a1 : (q == 2) ? a2 : a3;
            cc += __shfl_xor_sync(0xFFFFFFFFu, cc, 4);
            cc += __shfl_xor_sync(0xFFFFFFFFu, cc, 2);
            cc += __shfl_xor_sync(0xFFFFFFFFu, cc, 1);
            if ((lane & 7) == 0)
                pbuf[(g + q) * 17 + warp] = cc;

            xc0 = xn0; xc1 = xn1; xc2 = xn2; xc3 = xn3;
        }

        // One barrier per chunk: pbuf complete, AND (by the same barrier on the
        // previous iteration) the other buffer's y-drain has finished before
        // it gets overwritten next iteration.
        __syncthreads();

        if (tid < QB) {
            float s = s_base;
#pragma unroll
            for (int w = 0; w < NWARP; w++) s += pbuf[tid * 17 + w];
            y[bchunk + tid] = s;
        }
        // no second barrier: next chunk writes part[parity^1]; the drain of
        // pbuf completes before the barrier at the END of the next chunk,
        // which is before part[parity] is written again (chunk after next).
    }
}

// ---------------------------------------------------------------------------
// kernel_launch: inputs in setup_inputs order:
//   0:x (B,F)  1:W1 (F,H)  2:b1 (F,H)  3:W2 (F,H)  4:b2 (F)  5:theta (F)  6:bias (1)
// output: y_pred (B) then nn_theta (F), fp32.
// ---------------------------------------------------------------------------
extern "C" void kernel_launch(void* const* d_in, const int* in_sizes, int n_in,
                              void* d_out, int out_size) {
    const float* x     = (const float*)d_in[0];
    const float* W1    = (const float*)d_in[1];
    const float* b1    = (const float*)d_in[2];
    const float* W2    = (const float*)d_in[3];
    const float* b2    = (const float*)d_in[4];
    const float* theta = (const float*)d_in[5];
    const float* bias  = (const float*)d_in[6];
    float* out = (float*)d_out;

    neural_unilasso_kernel<<<GRID, THREADS>>>(
        x, W1, b1, W2, b2, theta, bias, out, out + B_TOT);
}

// round 11
// speedup vs baseline: 1.2154x; 1.0019x over previous
#include <cuda_runtime.h>
#include <cuda_fp16.h>
#include <math.h>

#define B_TOT 32768
#define F_TOT 512
#define H_TOT 10

#define THREADS 512          // 16 warps; warp w covers features [32w, 32w+32)
#define NWARP (THREADS / 32)
#define CHUNK 32             // batches per block (R6-proven schedule)
#define NB 4                 // batches per inner group (2 half2 pairs)

__device__ __forceinline__ __half2 tanh2_fast(__half2 v) {
    unsigned a = *reinterpret_cast<unsigned*>(&v), r;
    asm("tanh.approx.f16x2 %0, %1;" : "=r"(r) : "r"(a));
    return *reinterpret_cast<__half2*>(&r);
}

__device__ __forceinline__ float warp_sum(float v) {
#pragma unroll
    for (int off = 16; off > 0; off >>= 1)
        v += __shfl_xor_sync(0xFFFFFFFFu, v, off);
    return v;
}

// ---------------------------------------------------------------------------
// R6 scaffold (grid=1024, CHUNK=32, depth-1 prefetch) with R7's cheaper
// accumulation tail: per 2 hidden units, products accumulate in half2
// (1 HMUL2 + 1 HFMA2 per pair) and dump to fp32 once -> ~16% fewer issues
// per group at identical MUFU load. fp32 accumulation beyond 2-term blocks.
// ---------------------------------------------------------------------------
__global__ __launch_bounds__(THREADS, 2)
void neural_unilasso_kernel(const float* __restrict__ x,
                            const float* __restrict__ W1,
                            const float* __restrict__ b1,
                            const float* __restrict__ W2,
                            const float* __restrict__ b2,
                            const float* __restrict__ theta,
                            const float* __restrict__ bias,
                            float* __restrict__ y,
                            float* __restrict__ y_theta) {
    __shared__ float part[CHUNK * 17];   // [batch][warp], padded stride
    __shared__ float s_red[NWARP];
    __shared__ float s_base;

    const int tid  = threadIdx.x;
    const int lane = tid & 31;
    const int warp = tid >> 5;
    const int f    = warp * 32 + lane;   // THREADS == F_TOT

    // ---- prologue: params + softplus + csum ----
    const float th = theta[f];
    const float st = log1pf(expf(th));           // softplus
    if (blockIdx.x == 0) y_theta[f] = st;        // nn_theta output

    __half2 w1h[H_TOT], b1h[H_TOT], w2h[H_TOT];
#pragma unroll
    for (int h = 0; h < H_TOT; h++) {
        float w1 = __ldg(&W1[f * H_TOT + h]);
        float bb = __ldg(&b1[f * H_TOT + h]);
        float w2 = __ldg(&W2[f * H_TOT + h]) * st;
        w1h[h] = __floats2half2_rn(w1, w1);
        b1h[h] = __floats2half2_rn(bb, bb);
        w2h[h] = __floats2half2_rn(w2, w2);
    }
    {
        float c = warp_sum(b2[f] * st);
        if (lane == 0) s_red[warp] = c;
        __syncthreads();
        if (tid == 0) {
            float s = bias[0];
#pragma unroll
            for (int w = 0; w < NWARP; w++) s += s_red[w];
            s_base = s;
        }
        __syncthreads();
    }

    const int bchunk = blockIdx.x * CHUNK;
    const float* xp = x + (size_t)bchunk * F_TOT + f;

    // depth-1 prefetch (R6-proven; depth-2 regressed in R7)
    float xc0 = __ldg(xp + 0 * F_TOT);
    float xc1 = __ldg(xp + 1 * F_TOT);
    float xc2 = __ldg(xp + 2 * F_TOT);
    float xc3 = __ldg(xp + 3 * F_TOT);

#pragma unroll 1
    for (int g = 0; g < CHUNK; g += NB) {
        float xn0, xn1, xn2, xn3;
        if (g + NB < CHUNK) {
            xn0 = __ldg(xp + (size_t)(g + NB + 0) * F_TOT);
            xn1 = __ldg(xp + (size_t)(g + NB + 1) * F_TOT);
            xn2 = __ldg(xp + (size_t)(g + NB + 2) * F_TOT);
            xn3 = __ldg(xp + (size_t)(g + NB + 3) * F_TOT);
        }

        const __half2 x01 = __floats2half2_rn(xc0, xc1);
        const __half2 x23 = __floats2half2_rn(xc2, xc3);

        float a0 = 0.f, a1 = 0.f, a2 = 0.f, a3 = 0.f;
#pragma unroll
        for (int hb = 0; hb < H_TOT; hb += 2) {
            __half2 p01a = __hfma2(x01, w1h[hb],     b1h[hb]);
            __half2 p23a = __hfma2(x23, w1h[hb],     b1h[hb]);
            __half2 p01b = __hfma2(x01, w1h[hb + 1], b1h[hb + 1]);
            __half2 p23b = __hfma2(x23, w1h[hb + 1], b1h[hb + 1]);
            __half2 t01a = tanh2_fast(p01a);
            __half2 t23a = tanh2_fast(p23a);
            __half2 t01b = tanh2_fast(p01b);
            __half2 t23b = tanh2_fast(p23b);
            __half2 c01 = __hmul2(t01a, w2h[hb]);
            __half2 c23 = __hmul2(t23a, w2h[hb]);
            c01 = __hfma2(t01b, w2h[hb + 1], c01);
            c23 = __hfma2(t23b, w2h[hb + 1], c23);
            float2 f01 = __half22float2(c01);
            float2 f23 = __half22float2(c23);
            a0 += f01.x;
            a1 += f01.y;
            a2 += f23.x;
            a3 += f23.y;
        }

        // folded 4-accumulator warp reduction (11 SHFL)
        a0 += __shfl_xor_sync(0xFFFFFFFFu, a0, 16);
        a1 += __shfl_xor_sync(0xFFFFFFFFu, a1, 16);
        a2 += __shfl_xor_sync(0xFFFFFFFFu, a2, 16);
        a3 += __shfl_xor_sync(0xFFFFFFFFu, a3, 16);
        a0 += __shfl_xor_sync(0xFFFFFFFFu, a0, 8);
        a1 += __shfl_xor_sync(0xFFFFFFFFu, a1, 8);
        a2 += __shfl_xor_sync(0xFFFFFFFFu, a2, 8);
        a3 += __shfl_xor_sync(0xFFFFFFFFu, a3, 8);
        int q = (lane >> 3) & 3;
        float c = (q == 0) ? a0 : (q == 1) ? a1 : (q == 2) ? a2 : a3;
        c += __shfl_xor_sync(0xFFFFFFFFu, c, 4);
        c += __shfl_xor_sync(0xFFFFFFFFu, c, 2);
        c += __shfl_xor_sync(0xFFFFFFFFu, c, 1);
        if ((lane & 7) == 0)
            part[(g + q) * 17 + warp] = c;

        xc0 = xn0; xc1 = xn1; xc2 = xn2; xc3 = xn3;
    }
    __syncthreads();

    if (tid < CHUNK) {
        float s = s_base;
#pragma unroll
        for (int w = 0; w < NWARP; w++) s += part[tid * 17 + w];
        y[bchunk + tid] = s;
    }
}

// ---------------------------------------------------------------------------
// kernel_launch: inputs in setup_inputs order:
//   0:x (B,F)  1:W1 (F,H)  2:b1 (F,H)  3:W2 (F,H)  4:b2 (F)  5:theta (F)  6:bias (1)
// output: y_pred (B) then nn_theta (F), fp32.
// ---------------------------------------------------------------------------
extern "C" void kernel_launch(void* const* d_in, const int* in_sizes, int n_in,
                              void* d_out, int out_size) {
    const float* x     = (const float*)d_in[0];
    const float* W1    = (const float*)d_in[1];
    const float* b1    = (const float*)d_in[2];
    const float* W2    = (const float*)d_in[3];
    const float* b2    = (const float*)d_in[4];
    const float* theta = (const float*)d_in[5];
    const float* bias  = (const float*)d_in[6];
    float* out = (float*)d_out;

    neural_unilasso_kernel<<<B_TOT / CHUNK, THREADS>>>(
        x, W1, b1, W2, b2, theta, bias, out, out + B_TOT);
}